// round 3
// baseline (speedup 1.0000x reference)
#include <cuda_runtime.h>
#include <math.h>

#define B_ 8
#define N_ 1024
#define C_ 768
#define H_ 12
#define DH_ 64
#define NIMG_ 784

typedef unsigned long long ull;

// Scratch (static device arrays: allocation-free per harness rules)
__device__ float g_qkv[B_ * N_ * 3 * C_];       // [8192][2304]
__device__ float g_q[B_ * H_ * N_ * DH_];       // [bh][n][d]
__device__ float g_k[B_ * H_ * N_ * DH_];
__device__ float g_v[B_ * H_ * N_ * DH_];
__device__ float g_ao[B_ * N_ * C_];            // attention out, [b*N+n][C]

__device__ __forceinline__ void ffma2(ull& d, ull a, ull b) {
    asm("fma.rn.f32x2 %0, %1, %2, %0;" : "+l"(d) : "l"(a), "l"(b));
}
__device__ __forceinline__ float ull_lo(ull v) { return __uint_as_float((unsigned)(v)); }
__device__ __forceinline__ float ull_hi(ull v) { return __uint_as_float((unsigned)(v >> 32)); }

// ---------------------------------------------------------------------------
// Tiled SGEMM with packed f32x2 FFMA: out[m][n] = dot(A[m][:], W[n][:]) + bias[n]
// A: [M][K] row-major, W: [Nout][K] row-major. BM=BN=128, BK=16, 256 threads,
// 8x8 register tile per thread. A stored DUPLICATED in smem so (a,a) pairs
// come straight from LDS.128 (no packing movs). 32 FFMA2 = 128 FLOP per k.
// ---------------------------------------------------------------------------
__global__ void __launch_bounds__(256) sgemm_bias_kernel(
    const float* __restrict__ A, const float* __restrict__ W,
    const float* __restrict__ bias, float* __restrict__ out,
    int M, int Nout, int K)
{
    __shared__ float sA[16][260];  // [k][2*m duplicated], stride 260 (16B-aligned)
    __shared__ float sB[16][136];  // [k][n], stride 136 (16B-aligned)

    const int t = threadIdx.x;
    const int ty = t >> 4;        // 0..15 -> 8 rows each
    const int tx = t & 15;        // 0..15 -> 8 cols each
    const int m0 = blockIdx.y * 128;
    const int n0 = blockIdx.x * 128;

    ull acc[8][4];
#pragma unroll
    for (int i = 0; i < 8; i++)
#pragma unroll
        for (int j = 0; j < 4; j++) acc[i][j] = 0ull;

    for (int k0 = 0; k0 < K; k0 += 16) {
#pragma unroll
        for (int i = 0; i < 2; i++) {
            int idx4 = t + i * 256;          // 0..511
            int r = idx4 >> 2;               // 0..127
            int c4 = (idx4 & 3) * 4;
            float4 va = *(const float4*)(A + (size_t)(m0 + r) * K + k0 + c4);
            sA[c4 + 0][2 * r] = va.x; sA[c4 + 0][2 * r + 1] = va.x;
            sA[c4 + 1][2 * r] = va.y; sA[c4 + 1][2 * r + 1] = va.y;
            sA[c4 + 2][2 * r] = va.z; sA[c4 + 2][2 * r + 1] = va.z;
            sA[c4 + 3][2 * r] = va.w; sA[c4 + 3][2 * r + 1] = va.w;
            float4 vb = *(const float4*)(W + (size_t)(n0 + r) * K + k0 + c4);
            sB[c4 + 0][r] = vb.x; sB[c4 + 1][r] = vb.y;
            sB[c4 + 2][r] = vb.z; sB[c4 + 3][r] = vb.w;
        }
        __syncthreads();

#pragma unroll
        for (int kk = 0; kk < 16; kk++) {
            const ulonglong2* pa = (const ulonglong2*)&sA[kk][ty * 16];
            ulonglong2 a01 = pa[0], a23 = pa[1], a45 = pa[2], a67 = pa[3];
            const ulonglong2* pb = (const ulonglong2*)&sB[kk][tx * 8];
            ulonglong2 b01 = pb[0], b23 = pb[1];
            ull av[8] = {a01.x, a01.y, a23.x, a23.y, a45.x, a45.y, a67.x, a67.y};
            ull bv[4] = {b01.x, b01.y, b23.x, b23.y};
#pragma unroll
            for (int i = 0; i < 8; i++)
#pragma unroll
                for (int jp = 0; jp < 4; jp++) ffma2(acc[i][jp], av[i], bv[jp]);
        }
        __syncthreads();
    }

    // epilogue: rows m0+ty*8+i, cols n0+tx*8 .. +7
    const float4 bias0 = *(const float4*)(bias + n0 + tx * 8);
    const float4 bias1 = *(const float4*)(bias + n0 + tx * 8 + 4);
#pragma unroll
    for (int i = 0; i < 8; i++) {
        size_t ro = (size_t)(m0 + ty * 8 + i) * Nout + n0 + tx * 8;
        float4 o0, o1;
        o0.x = ull_lo(acc[i][0]) + bias0.x; o0.y = ull_hi(acc[i][0]) + bias0.y;
        o0.z = ull_lo(acc[i][1]) + bias0.z; o0.w = ull_hi(acc[i][1]) + bias0.w;
        o1.x = ull_lo(acc[i][2]) + bias1.x; o1.y = ull_hi(acc[i][2]) + bias1.y;
        o1.z = ull_lo(acc[i][3]) + bias1.z; o1.w = ull_hi(acc[i][3]) + bias1.w;
        *(float4*)(out + ro) = o0;
        *(float4*)(out + ro + 4) = o1;
    }
}

// ---------------------------------------------------------------------------
// RoPE2D + split qkv into q,k,v with [b*H+h][n][d] layout.
// ---------------------------------------------------------------------------
__global__ void rope_split_kernel(const int* __restrict__ pos2d)
{
    int idx = blockIdx.x * blockDim.x + threadIdx.x;
    const int total = B_ * N_ * H_ * DH_;
    if (idx >= total) return;

    int d = idx & 63;
    int h = (idx >> 6) % H_;
    int n = (idx / (H_ * DH_)) % N_;
    int b = idx / (N_ * H_ * DH_);

    const float* row = g_qkv + (size_t)(b * N_ + n) * (3 * C_);
    float qv = row[h * 64 + d];
    float kv = row[C_ + h * 64 + d];
    float vv = row[2 * C_ + h * 64 + d];

    if (n < NIMG_) {
        int half = d >> 5;               // 0 = y, 1 = x
        int dl = d & 31;
        int f = dl & 15;
        int pos = pos2d[((size_t)b * NIMG_ + n) * 2 + half];
        // 100^(-f/16) = exp2(-f * log2(100)/16)
        float inv = exp2f(-0.41524101186f * (float)f);
        float ang = (float)pos * inv;
        float s, c;
        sincosf(ang, &s, &c);
        int pd = (dl < 16) ? (d + 16) : (d - 16);
        float sign = (dl < 16) ? -1.0f : 1.0f;
        float qp = row[h * 64 + pd];
        float kp = row[C_ + h * 64 + pd];
        qv = qv * c + sign * qp * s;
        kv = kv * c + sign * kp * s;
    }

    size_t o = ((size_t)(b * H_ + h) * N_ + n) * DH_ + d;
    g_q[o] = qv; g_k[o] = kv; g_v[o] = vv;
}

// ---------------------------------------------------------------------------
// Flash-style fp32 attention. Grid: (N/128 q-tiles, B*H). 128 threads.
// BQ=128, BK=64, Dh=64. 8x8 register tiles, LDS.128 everywhere.
// Dynamic smem: sQ[64][132] | sK[64][68] | sV[64][68] | sP[64][132]
// ---------------------------------------------------------------------------
#define SQ_OFF 0
#define SK_OFF (64 * 132)
#define SV_OFF (SK_OFF + 64 * 68)
#define SP_OFF (SV_OFF + 64 * 68)
#define ATTN_SMEM_FLOATS (SP_OFF + 64 * 132)
#define ATTN_SMEM_BYTES (ATTN_SMEM_FLOATS * 4)

__global__ void __launch_bounds__(128) attn_kernel(float* __restrict__ out)
{
    extern __shared__ float sm[];
    float* sQ = sm + SQ_OFF;   // [d][q], stride 132
    float* sK = sm + SK_OFF;   // [d][key], stride 68
    float* sV = sm + SV_OFF;   // [key][d], stride 68
    float* sP = sm + SP_OFF;   // [key][q], stride 132

    const int t = threadIdx.x;
    const int ty = t >> 3;        // 0..15 -> 8 q-rows each
    const int tx = t & 7;         // 0..7  -> 8 cols each
    const int bh = blockIdx.y;
    const int q0 = blockIdx.x * 128;

    const float* Q = g_q + ((size_t)bh * N_ + q0) * DH_;
    const float* K = g_k + (size_t)bh * N_ * DH_;
    const float* V = g_v + (size_t)bh * N_ * DH_;

    // Load Q tile transposed (2048 float4, 16 per thread): sQ[d][q]
#pragma unroll
    for (int i = 0; i < 16; i++) {
        int idx4 = t + i * 128;
        int r = idx4 >> 4;              // 0..127 (q row)
        int c4 = (idx4 & 15) * 4;       // d
        float4 v4 = *(const float4*)(Q + (size_t)r * 64 + c4);
        sQ[(c4 + 0) * 132 + r] = v4.x; sQ[(c4 + 1) * 132 + r] = v4.y;
        sQ[(c4 + 2) * 132 + r] = v4.z; sQ[(c4 + 3) * 132 + r] = v4.w;
    }

    float m_[8], l_[8], o_[8][8];
#pragma unroll
    for (int i = 0; i < 8; i++) {
        m_[i] = -1e30f; l_[i] = 0.f;
#pragma unroll
        for (int j = 0; j < 8; j++) o_[i][j] = 0.f;
    }

    for (int kb = 0; kb < N_; kb += 64) {
        __syncthreads();  // previous iteration's readers of sK/sV/sP done
#pragma unroll
        for (int i = 0; i < 8; i++) {
            int idx4 = t + i * 128;
            int r = idx4 >> 4;          // 0..63 (key)
            int c4 = (idx4 & 15) * 4;   // d
            float4 k4 = *(const float4*)(K + (size_t)(kb + r) * 64 + c4);
            sK[(c4 + 0) * 68 + r] = k4.x; sK[(c4 + 1) * 68 + r] = k4.y;
            sK[(c4 + 2) * 68 + r] = k4.z; sK[(c4 + 3) * 68 + r] = k4.w;
            float4 v4 = *(const float4*)(V + (size_t)(kb + r) * 64 + c4);
            *(float4*)&sV[r * 68 + c4] = v4;
        }
        __syncthreads();

        // S = Q * K^T  (rows = queries, cols = keys)
        float s[8][8];
#pragma unroll
        for (int i = 0; i < 8; i++)
#pragma unroll
            for (int j = 0; j < 8; j++) s[i][j] = 0.f;
#pragma unroll
        for (int kk = 0; kk < 64; kk++) {
            float4 a0 = *(const float4*)&sQ[kk * 132 + ty * 8];
            float4 a1 = *(const float4*)&sQ[kk * 132 + ty * 8 + 4];
            float4 b0 = *(const float4*)&sK[kk * 68 + tx * 8];
            float4 b1 = *(const float4*)&sK[kk * 68 + tx * 8 + 4];
            float a[8] = {a0.x, a0.y, a0.z, a0.w, a1.x, a1.y, a1.z, a1.w};
            float b[8] = {b0.x, b0.y, b0.z, b0.w, b1.x, b1.y, b1.z, b1.w};
#pragma unroll
            for (int i = 0; i < 8; i++)
#pragma unroll
                for (int j = 0; j < 8; j++) s[i][j] = fmaf(a[i], b[j], s[i][j]);
        }

        const float scale = 0.125f;  // 64^-0.5
#pragma unroll
        for (int i = 0; i < 8; i++) {
            float rm = -1e30f;
#pragma unroll
            for (int j = 0; j < 8; j++) {
                s[i][j] *= scale;
                rm = fmaxf(rm, s[i][j]);
            }
#pragma unroll
            for (int off = 1; off < 8; off <<= 1)
                rm = fmaxf(rm, __shfl_xor_sync(0xffffffffu, rm, off));

            float mn = fmaxf(m_[i], rm);
            float corr = __expf(m_[i] - mn);
            m_[i] = mn;
            float rs = 0.f;
#pragma unroll
            for (int j = 0; j < 8; j++) {
                float p = __expf(s[i][j] - mn);
                s[i][j] = p;
                rs += p;
            }
#pragma unroll
            for (int off = 1; off < 8; off <<= 1)
                rs += __shfl_xor_sync(0xffffffffu, rs, off);
            l_[i] = l_[i] * corr + rs;
#pragma unroll
            for (int j = 0; j < 8; j++) o_[i][j] *= corr;
        }

        // stash P transposed: sP[key][q-row]
#pragma unroll
        for (int i = 0; i < 8; i++)
#pragma unroll
            for (int j = 0; j < 8; j++)
                sP[(tx * 8 + j) * 132 + ty * 8 + i] = s[i][j];
        __syncthreads();

        // O += P * V   (rows = queries, cols = head dims)
#pragma unroll
        for (int kk = 0; kk < 64; kk++) {
            float4 a0 = *(const float4*)&sP[kk * 132 + ty * 8];
            float4 a1 = *(const float4*)&sP[kk * 132 + ty * 8 + 4];
            float4 b0 = *(const float4*)&sV[kk * 68 + tx * 8];
            float4 b1 = *(const float4*)&sV[kk * 68 + tx * 8 + 4];
            float pa[8] = {a0.x, a0.y, a0.z, a0.w, a1.x, a1.y, a1.z, a1.w};
            float vb[8] = {b0.x, b0.y, b0.z, b0.w, b1.x, b1.y, b1.z, b1.w};
#pragma unroll
            for (int i = 0; i < 8; i++)
#pragma unroll
                for (int j = 0; j < 8; j++) o_[i][j] = fmaf(pa[i], vb[j], o_[i][j]);
        }
    }

    const int b = bh / H_;
    const int h = bh % H_;
#pragma unroll
    for (int i = 0; i < 8; i++) {
        float inv = 1.0f / l_[i];
        size_t ro = ((size_t)b * N_ + q0 + ty * 8 + i) * C_ + h * 64 + tx * 8;
#pragma unroll
        for (int j = 0; j < 8; j++)
            out[ro + j] = o_[i][j] * inv;
    }
}

// ---------------------------------------------------------------------------
extern "C" void kernel_launch(void* const* d_in, const int* in_sizes, int n_in,
                              void* d_out, int out_size)
{
    const float* x_t    = (const float*)d_in[0];
    const float* qkv_w  = (const float*)d_in[1];
    const float* qkv_b  = (const float*)d_in[2];
    const float* proj_w = (const float*)d_in[3];
    const float* proj_b = (const float*)d_in[4];
    const int*   pos2d  = (const int*)d_in[5];
    float* out = (float*)d_out;

    float *p_qkv, *p_ao;
    cudaGetSymbolAddress((void**)&p_qkv, g_qkv);
    cudaGetSymbolAddress((void**)&p_ao, g_ao);

    // 1) QKV GEMM: [8192,768] x [2304,768]^T -> [8192,2304]
    {
        dim3 grid((3 * C_) / 128, (B_ * N_) / 128);
        sgemm_bias_kernel<<<grid, 256>>>(x_t, qkv_w, qkv_b, p_qkv,
                                         B_ * N_, 3 * C_, C_);
    }
    // 2) RoPE2D + split/transpose
    {
        int total = B_ * N_ * H_ * DH_;
        rope_split_kernel<<<(total + 255) / 256, 256>>>(pos2d);
    }
    // 3) Attention
    {
        cudaFuncSetAttribute(attn_kernel,
                             cudaFuncAttributeMaxDynamicSharedMemorySize,
                             ATTN_SMEM_BYTES);
        dim3 grid(N_ / 128, B_ * H_);
        attn_kernel<<<grid, 128, ATTN_SMEM_BYTES>>>(p_ao);
    }
    // 4) Output projection: [8192,768] x [768,768]^T -> [8192,768]
    {
        dim3 grid(C_ / 128, (B_ * N_) / 128);
        sgemm_bias_kernel<<<grid, 256>>>(p_ao, proj_w, proj_b, out,
                                         B_ * N_, C_, C_);
    }
}

// round 4
// speedup vs baseline: 2.0692x; 2.0692x over previous
#include <cuda_runtime.h>
#include <math.h>

#define B_ 8
#define N_ 1024
#define C_ 768
#define H_ 12
#define DH_ 64
#define NIMG_ 784

// Scratch (static device arrays: allocation-free per harness rules)
__device__ float g_qkv[B_ * N_ * 3 * C_];       // [8192][2304]
__device__ float g_q[B_ * H_ * N_ * DH_];       // [bh][n][d]
__device__ float g_k[B_ * H_ * N_ * DH_];
__device__ float g_v[B_ * H_ * N_ * DH_];
__device__ float g_ao[B_ * N_ * C_];            // attention out, [b*N+n][C]

__device__ __forceinline__ unsigned f2tf32(float f) {
    unsigned u;
    asm("cvt.rna.tf32.f32 %0, %1;" : "=r"(u) : "f"(f));
    return u;
}

__device__ __forceinline__ void mma_tf32(float* d, const unsigned* a, const unsigned* b) {
    asm volatile(
        "mma.sync.aligned.m16n8k8.row.col.f32.tf32.tf32.f32 "
        "{%0,%1,%2,%3}, {%4,%5,%6,%7}, {%8,%9}, {%0,%1,%2,%3};"
        : "+f"(d[0]), "+f"(d[1]), "+f"(d[2]), "+f"(d[3])
        : "r"(a[0]), "r"(a[1]), "r"(a[2]), "r"(a[3]), "r"(b[0]), "r"(b[1]));
}

// ---------------------------------------------------------------------------
// TF32 tensor-core GEMM: out[m][n] = dot(A[m][:], W[n][:]) + bias[n]
// A: [M][K] row-major, W: [Nout][K] row-major (= col-major B, matching
// mma .row.col). Block 128x128, BK=16, 256 threads = 8 warps in 2(m)x4(n),
// warp tile 64x32 -> 4 m-frags x 4 n-frags of m16n8k8, 2 k-steps per BK.
// Register-prefetch pipeline over single-buffered smem.
// ---------------------------------------------------------------------------
#define BKg 16
#define SSTR 20  // smem row stride (uints): pad 4 -> conflict-free frag reads

__global__ void __launch_bounds__(256, 2) mma_gemm_bias(
    const float* __restrict__ A, const float* __restrict__ W,
    const float* __restrict__ bias, float* __restrict__ out,
    int M, int Nout, int K)
{
    __shared__ unsigned sA[128 * SSTR];
    __shared__ unsigned sB[128 * SSTR];

    const int t = threadIdx.x;
    const int lane = t & 31;
    const int warp = t >> 5;
    const int wm = (warp & 1) * 64;       // warp m offset in block
    const int wn = (warp >> 1) * 32;      // warp n offset in block
    const int m0 = blockIdx.y * 128;
    const int n0 = blockIdx.x * 128;

    // global->reg tile mapping: idx = t + i*256 in [0,512); r=idx>>2, c4=(idx&3)*4
    const int r0g = (t + 0) >> 2, c0g = ((t + 0) & 3) * 4;
    const int r1g = (t + 256) >> 2, c1g = ((t + 256) & 3) * 4;

    float acc[4][4][4];
#pragma unroll
    for (int i = 0; i < 4; i++)
#pragma unroll
        for (int j = 0; j < 4; j++)
#pragma unroll
            for (int v = 0; v < 4; v++) acc[i][j][v] = 0.f;

    float4 pa0, pa1, pb0, pb1;
    // prefetch tile 0
    pa0 = *(const float4*)(A + (size_t)(m0 + r0g) * K + c0g);
    pa1 = *(const float4*)(A + (size_t)(m0 + r1g) * K + c1g);
    pb0 = *(const float4*)(W + (size_t)(n0 + r0g) * K + c0g);
    pb1 = *(const float4*)(W + (size_t)(n0 + r1g) * K + c1g);

    for (int k0 = 0;;) {
        // store prefetched tile (tf32-rounded)
        {
            uint4 ua0 = make_uint4(f2tf32(pa0.x), f2tf32(pa0.y), f2tf32(pa0.z), f2tf32(pa0.w));
            uint4 ua1 = make_uint4(f2tf32(pa1.x), f2tf32(pa1.y), f2tf32(pa1.z), f2tf32(pa1.w));
            uint4 ub0 = make_uint4(f2tf32(pb0.x), f2tf32(pb0.y), f2tf32(pb0.z), f2tf32(pb0.w));
            uint4 ub1 = make_uint4(f2tf32(pb1.x), f2tf32(pb1.y), f2tf32(pb1.z), f2tf32(pb1.w));
            *(uint4*)&sA[r0g * SSTR + c0g] = ua0;
            *(uint4*)&sA[r1g * SSTR + c1g] = ua1;
            *(uint4*)&sB[r0g * SSTR + c0g] = ub0;
            *(uint4*)&sB[r1g * SSTR + c1g] = ub1;
        }
        __syncthreads();

        const bool has_next = (k0 + BKg) < K;
        if (has_next) {
            int kn = k0 + BKg;
            pa0 = *(const float4*)(A + (size_t)(m0 + r0g) * K + kn + c0g);
            pa1 = *(const float4*)(A + (size_t)(m0 + r1g) * K + kn + c1g);
            pb0 = *(const float4*)(W + (size_t)(n0 + r0g) * K + kn + c0g);
            pb1 = *(const float4*)(W + (size_t)(n0 + r1g) * K + kn + c1g);
        }

        const int fr = lane >> 2;   // 0..7
        const int fc = lane & 3;    // 0..3
#pragma unroll
        for (int ks = 0; ks < 2; ks++) {
            unsigned areg[4][4], breg[4][2];
#pragma unroll
            for (int mf = 0; mf < 4; mf++) {
                const unsigned* base = &sA[(wm + mf * 16 + fr) * SSTR + ks * 8 + fc];
                areg[mf][0] = base[0];
                areg[mf][1] = base[8 * SSTR];
                areg[mf][2] = base[4];
                areg[mf][3] = base[8 * SSTR + 4];
            }
#pragma unroll
            for (int nf = 0; nf < 4; nf++) {
                const unsigned* base = &sB[(wn + nf * 8 + fr) * SSTR + ks * 8 + fc];
                breg[nf][0] = base[0];
                breg[nf][1] = base[4];
            }
#pragma unroll
            for (int mf = 0; mf < 4; mf++)
#pragma unroll
                for (int nf = 0; nf < 4; nf++)
                    mma_tf32(acc[mf][nf], areg[mf], breg[nf]);
        }
        __syncthreads();

        if (!has_next) break;
        k0 += BKg;
    }

    // epilogue: D[r][2c] layout; float2 stores with bias
    const int fr = lane >> 2;
    const int fc = lane & 3;
#pragma unroll
    for (int mf = 0; mf < 4; mf++) {
        int row = m0 + wm + mf * 16 + fr;
#pragma unroll
        for (int nf = 0; nf < 4; nf++) {
            int col = n0 + wn + nf * 8 + 2 * fc;
            float bx = bias[col], by = bias[col + 1];
            float2 lo = make_float2(acc[mf][nf][0] + bx, acc[mf][nf][1] + by);
            float2 hi = make_float2(acc[mf][nf][2] + bx, acc[mf][nf][3] + by);
            *(float2*)(out + (size_t)row * Nout + col) = lo;
            *(float2*)(out + (size_t)(row + 8) * Nout + col) = hi;
        }
    }
}

// ---------------------------------------------------------------------------
// RoPE2D + split qkv into q,k,v with [b*H+h][n][d] layout.
// ---------------------------------------------------------------------------
__global__ void rope_split_kernel(const int* __restrict__ pos2d)
{
    int idx = blockIdx.x * blockDim.x + threadIdx.x;
    const int total = B_ * N_ * H_ * DH_;
    if (idx >= total) return;

    int d = idx & 63;
    int h = (idx >> 6) % H_;
    int n = (idx / (H_ * DH_)) % N_;
    int b = idx / (N_ * H_ * DH_);

    const float* row = g_qkv + (size_t)(b * N_ + n) * (3 * C_);
    float qv = row[h * 64 + d];
    float kv = row[C_ + h * 64 + d];
    float vv = row[2 * C_ + h * 64 + d];

    if (n < NIMG_) {
        int half = d >> 5;               // 0 = y, 1 = x
        int dl = d & 31;
        int f = dl & 15;
        int pos = pos2d[((size_t)b * NIMG_ + n) * 2 + half];
        // 100^(-f/16) = exp2(-f * log2(100)/16)
        float inv = exp2f(-0.41524101186f * (float)f);
        float ang = (float)pos * inv;
        float s, c;
        sincosf(ang, &s, &c);
        int pd = (dl < 16) ? (d + 16) : (d - 16);
        float sign = (dl < 16) ? -1.0f : 1.0f;
        float qp = row[h * 64 + pd];
        float kp = row[C_ + h * 64 + pd];
        qv = qv * c + sign * qp * s;
        kv = kv * c + sign * kp * s;
    }

    size_t o = ((size_t)(b * H_ + h) * N_ + n) * DH_ + d;
    g_q[o] = qv; g_k[o] = kv; g_v[o] = vv;
}

// ---------------------------------------------------------------------------
// Flash-style fp32 attention (R2 measured-good version).
// Grid: (N/64 q-tiles, B*H). 128 threads. BQ=BK=64, Dh=64.
// ---------------------------------------------------------------------------
__global__ void __launch_bounds__(128) attn_kernel(float* __restrict__ out)
{
    __shared__ float sQ[64][65];  // [d][q-row] transposed
    __shared__ float sK[64][65];  // [d][key]   transposed
    __shared__ float sV[64][64];  // [key][d]
    __shared__ float sP[64][65];  // [key][q-row] transposed

    const int t = threadIdx.x;
    const int ty = t >> 3;        // 4 q-rows each
    const int tx = t & 7;         // 8 cols each
    const int bh = blockIdx.y;
    const int q0 = blockIdx.x * 64;

    const float* Q = g_q + ((size_t)bh * N_ + q0) * DH_;
    const float* K = g_k + (size_t)bh * N_ * DH_;
    const float* V = g_v + (size_t)bh * N_ * DH_;

#pragma unroll
    for (int i = 0; i < 8; i++) {
        int idx4 = t + i * 128;
        int r = idx4 >> 4;
        int c4 = (idx4 & 15) * 4;
        float4 v4 = *(const float4*)(Q + r * 64 + c4);
        sQ[c4 + 0][r] = v4.x; sQ[c4 + 1][r] = v4.y;
        sQ[c4 + 2][r] = v4.z; sQ[c4 + 3][r] = v4.w;
    }

    float m_[4], l_[4], o_[4][8];
#pragma unroll
    for (int i = 0; i < 4; i++) {
        m_[i] = -1e30f; l_[i] = 0.f;
#pragma unroll
        for (int j = 0; j < 8; j++) o_[i][j] = 0.f;
    }

    for (int kb = 0; kb < N_; kb += 64) {
        __syncthreads();
#pragma unroll
        for (int i = 0; i < 8; i++) {
            int idx4 = t + i * 128;
            int r = idx4 >> 4;
            int c4 = (idx4 & 15) * 4;
            float4 k4 = *(const float4*)(K + (size_t)(kb + r) * 64 + c4);
            sK[c4 + 0][r] = k4.x; sK[c4 + 1][r] = k4.y;
            sK[c4 + 2][r] = k4.z; sK[c4 + 3][r] = k4.w;
            float4 v4 = *(const float4*)(V + (size_t)(kb + r) * 64 + c4);
            *(float4*)&sV[r][c4] = v4;
        }
        __syncthreads();

        float s[4][8];
#pragma unroll
        for (int i = 0; i < 4; i++)
#pragma unroll
            for (int j = 0; j < 8; j++) s[i][j] = 0.f;
#pragma unroll
        for (int kk = 0; kk < 64; kk++) {
            float a[4], b[8];
#pragma unroll
            for (int i = 0; i < 4; i++) a[i] = sQ[kk][ty * 4 + i];
#pragma unroll
            for (int j = 0; j < 8; j++) b[j] = sK[kk][tx * 8 + j];
#pragma unroll
            for (int i = 0; i < 4; i++)
#pragma unroll
                for (int j = 0; j < 8; j++) s[i][j] = fmaf(a[i], b[j], s[i][j]);
        }

        const float scale = 0.125f;  // 64^-0.5
#pragma unroll
        for (int i = 0; i < 4; i++) {
            float rm = -1e30f;
#pragma unroll
            for (int j = 0; j < 8; j++) {
                s[i][j] *= scale;
                rm = fmaxf(rm, s[i][j]);
            }
#pragma unroll
            for (int off = 1; off < 8; off <<= 1)
                rm = fmaxf(rm, __shfl_xor_sync(0xffffffffu, rm, off));

            float mn = fmaxf(m_[i], rm);
            float corr = __expf(m_[i] - mn);
            m_[i] = mn;
            float rs = 0.f;
#pragma unroll
            for (int j = 0; j < 8; j++) {
                float p = __expf(s[i][j] - mn);
                s[i][j] = p;
                rs += p;
            }
#pragma unroll
            for (int off = 1; off < 8; off <<= 1)
                rs += __shfl_xor_sync(0xffffffffu, rs, off);
            l_[i] = l_[i] * corr + rs;
#pragma unroll
            for (int j = 0; j < 8; j++) o_[i][j] *= corr;
        }

#pragma unroll
        for (int i = 0; i < 4; i++)
#pragma unroll
            for (int j = 0; j < 8; j++)
                sP[tx * 8 + j][ty * 4 + i] = s[i][j];
        __syncthreads();

#pragma unroll
        for (int kk = 0; kk < 64; kk++) {
            float pa[4], vb[8];
#pragma unroll
            for (int i = 0; i < 4; i++) pa[i] = sP[kk][ty * 4 + i];
#pragma unroll
            for (int j = 0; j < 8; j++) vb[j] = sV[kk][tx * 8 + j];
#pragma unroll
            for (int i = 0; i < 4; i++)
#pragma unroll
                for (int j = 0; j < 8; j++) o_[i][j] = fmaf(pa[i], vb[j], o_[i][j]);
        }
    }

    const int b = bh / H_;
    const int h = bh % H_;
#pragma unroll
    for (int i = 0; i < 4; i++) {
        float inv = 1.0f / l_[i];
        size_t ro = ((size_t)b * N_ + q0 + ty * 4 + i) * C_ + h * 64 + tx * 8;
#pragma unroll
        for (int j = 0; j < 8; j++)
            out[ro + j] = o_[i][j] * inv;
    }
}

// ---------------------------------------------------------------------------
extern "C" void kernel_launch(void* const* d_in, const int* in_sizes, int n_in,
                              void* d_out, int out_size)
{
    const float* x_t    = (const float*)d_in[0];
    const float* qkv_w  = (const float*)d_in[1];
    const float* qkv_b  = (const float*)d_in[2];
    const float* proj_w = (const float*)d_in[3];
    const float* proj_b = (const float*)d_in[4];
    const int*   pos2d  = (const int*)d_in[5];
    float* out = (float*)d_out;

    float *p_qkv, *p_ao;
    cudaGetSymbolAddress((void**)&p_qkv, g_qkv);
    cudaGetSymbolAddress((void**)&p_ao, g_ao);

    // 1) QKV GEMM: [8192,768] x [2304,768]^T -> [8192,2304]
    {
        dim3 grid((3 * C_) / 128, (B_ * N_) / 128);
        mma_gemm_bias<<<grid, 256>>>(x_t, qkv_w, qkv_b, p_qkv,
                                     B_ * N_, 3 * C_, C_);
    }
    // 2) RoPE2D + split/transpose
    {
        int total = B_ * N_ * H_ * DH_;
        rope_split_kernel<<<(total + 255) / 256, 256>>>(pos2d);
    }
    // 3) Attention
    {
        dim3 grid(N_ / 64, B_ * H_);
        attn_kernel<<<grid, 128>>>(p_ao);
    }
    // 4) Output projection: [8192,768] x [768,768]^T -> [8192,768]
    {
        dim3 grid(C_ / 128, (B_ * N_) / 128);
        mma_gemm_bias<<<grid, 256>>>(p_ao, proj_w, proj_b, out,
                                     B_ * N_, C_, C_);
    }
}

// round 5
// speedup vs baseline: 4.2160x; 2.0375x over previous
#include <cuda_runtime.h>
#include <math.h>

#define B_ 8
#define N_ 1024
#define C_ 768
#define H_ 12
#define DH_ 64
#define NIMG_ 784

// Scratch (static device arrays: allocation-free per harness rules)
__device__ float g_qkv[B_ * N_ * 3 * C_];       // [8192][2304]
__device__ float g_q[B_ * H_ * N_ * DH_];       // [bh][n][d]
__device__ float g_k[B_ * H_ * N_ * DH_];
__device__ float g_v[B_ * H_ * N_ * DH_];
__device__ float g_ao[B_ * N_ * C_];            // attention out, [b*N+n][C]

__device__ __forceinline__ unsigned f2tf32(float f) {
    unsigned u;
    asm("cvt.rna.tf32.f32 %0, %1;" : "=r"(u) : "f"(f));
    return u;
}

__device__ __forceinline__ void mma_tf32(float* d, const unsigned* a, const unsigned* b) {
    asm volatile(
        "mma.sync.aligned.m16n8k8.row.col.f32.tf32.tf32.f32 "
        "{%0,%1,%2,%3}, {%4,%5,%6,%7}, {%8,%9}, {%0,%1,%2,%3};"
        : "+f"(d[0]), "+f"(d[1]), "+f"(d[2]), "+f"(d[3])
        : "r"(a[0]), "r"(a[1]), "r"(a[2]), "r"(a[3]), "r"(b[0]), "r"(b[1]));
}

// ---------------------------------------------------------------------------
// TF32 tensor-core GEMM (unchanged from R4 — measured 96 TF/s)
// ---------------------------------------------------------------------------
#define BKg 16
#define SSTR 20

__global__ void __launch_bounds__(256, 2) mma_gemm_bias(
    const float* __restrict__ A, const float* __restrict__ W,
    const float* __restrict__ bias, float* __restrict__ out,
    int M, int Nout, int K)
{
    __shared__ unsigned sA[128 * SSTR];
    __shared__ unsigned sB[128 * SSTR];

    const int t = threadIdx.x;
    const int lane = t & 31;
    const int warp = t >> 5;
    const int wm = (warp & 1) * 64;
    const int wn = (warp >> 1) * 32;
    const int m0 = blockIdx.y * 128;
    const int n0 = blockIdx.x * 128;

    const int r0g = (t + 0) >> 2, c0g = ((t + 0) & 3) * 4;
    const int r1g = (t + 256) >> 2, c1g = ((t + 256) & 3) * 4;

    float acc[4][4][4];
#pragma unroll
    for (int i = 0; i < 4; i++)
#pragma unroll
        for (int j = 0; j < 4; j++)
#pragma unroll
            for (int v = 0; v < 4; v++) acc[i][j][v] = 0.f;

    float4 pa0, pa1, pb0, pb1;
    pa0 = *(const float4*)(A + (size_t)(m0 + r0g) * K + c0g);
    pa1 = *(const float4*)(A + (size_t)(m0 + r1g) * K + c1g);
    pb0 = *(const float4*)(W + (size_t)(n0 + r0g) * K + c0g);
    pb1 = *(const float4*)(W + (size_t)(n0 + r1g) * K + c1g);

    for (int k0 = 0;;) {
        {
            uint4 ua0 = make_uint4(f2tf32(pa0.x), f2tf32(pa0.y), f2tf32(pa0.z), f2tf32(pa0.w));
            uint4 ua1 = make_uint4(f2tf32(pa1.x), f2tf32(pa1.y), f2tf32(pa1.z), f2tf32(pa1.w));
            uint4 ub0 = make_uint4(f2tf32(pb0.x), f2tf32(pb0.y), f2tf32(pb0.z), f2tf32(pb0.w));
            uint4 ub1 = make_uint4(f2tf32(pb1.x), f2tf32(pb1.y), f2tf32(pb1.z), f2tf32(pb1.w));
            *(uint4*)&sA[r0g * SSTR + c0g] = ua0;
            *(uint4*)&sA[r1g * SSTR + c1g] = ua1;
            *(uint4*)&sB[r0g * SSTR + c0g] = ub0;
            *(uint4*)&sB[r1g * SSTR + c1g] = ub1;
        }
        __syncthreads();

        const bool has_next = (k0 + BKg) < K;
        if (has_next) {
            int kn = k0 + BKg;
            pa0 = *(const float4*)(A + (size_t)(m0 + r0g) * K + kn + c0g);
            pa1 = *(const float4*)(A + (size_t)(m0 + r1g) * K + kn + c1g);
            pb0 = *(const float4*)(W + (size_t)(n0 + r0g) * K + kn + c0g);
            pb1 = *(const float4*)(W + (size_t)(n0 + r1g) * K + kn + c1g);
        }

        const int fr = lane >> 2;
        const int fc = lane & 3;
#pragma unroll
        for (int ks = 0; ks < 2; ks++) {
            unsigned areg[4][4], breg[4][2];
#pragma unroll
            for (int mf = 0; mf < 4; mf++) {
                const unsigned* base = &sA[(wm + mf * 16 + fr) * SSTR + ks * 8 + fc];
                areg[mf][0] = base[0];
                areg[mf][1] = base[8 * SSTR];
                areg[mf][2] = base[4];
                areg[mf][3] = base[8 * SSTR + 4];
            }
#pragma unroll
            for (int nf = 0; nf < 4; nf++) {
                const unsigned* base = &sB[(wn + nf * 8 + fr) * SSTR + ks * 8 + fc];
                breg[nf][0] = base[0];
                breg[nf][1] = base[4];
            }
#pragma unroll
            for (int mf = 0; mf < 4; mf++)
#pragma unroll
                for (int nf = 0; nf < 4; nf++)
                    mma_tf32(acc[mf][nf], areg[mf], breg[nf]);
        }
        __syncthreads();

        if (!has_next) break;
        k0 += BKg;
    }

    const int fr = lane >> 2;
    const int fc = lane & 3;
#pragma unroll
    for (int mf = 0; mf < 4; mf++) {
        int row = m0 + wm + mf * 16 + fr;
#pragma unroll
        for (int nf = 0; nf < 4; nf++) {
            int col = n0 + wn + nf * 8 + 2 * fc;
            float bx = bias[col], by = bias[col + 1];
            float2 lo = make_float2(acc[mf][nf][0] + bx, acc[mf][nf][1] + by);
            float2 hi = make_float2(acc[mf][nf][2] + bx, acc[mf][nf][3] + by);
            *(float2*)(out + (size_t)row * Nout + col) = lo;
            *(float2*)(out + (size_t)(row + 8) * Nout + col) = hi;
        }
    }
}

// ---------------------------------------------------------------------------
// RoPE2D + split qkv into q,k,v with [b*H+h][n][d] layout.
// ---------------------------------------------------------------------------
__global__ void rope_split_kernel(const int* __restrict__ pos2d)
{
    int idx = blockIdx.x * blockDim.x + threadIdx.x;
    const int total = B_ * N_ * H_ * DH_;
    if (idx >= total) return;

    int d = idx & 63;
    int h = (idx >> 6) % H_;
    int n = (idx / (H_ * DH_)) % N_;
    int b = idx / (N_ * H_ * DH_);

    const float* row = g_qkv + (size_t)(b * N_ + n) * (3 * C_);
    float qv = row[h * 64 + d];
    float kv = row[C_ + h * 64 + d];
    float vv = row[2 * C_ + h * 64 + d];

    if (n < NIMG_) {
        int half = d >> 5;
        int dl = d & 31;
        int f = dl & 15;
        int pos = pos2d[((size_t)b * NIMG_ + n) * 2 + half];
        float inv = exp2f(-0.41524101186f * (float)f);  // 100^(-f/16)
        float ang = (float)pos * inv;
        float s, c;
        sincosf(ang, &s, &c);
        int pd = (dl < 16) ? (d + 16) : (d - 16);
        float sign = (dl < 16) ? -1.0f : 1.0f;
        float qp = row[h * 64 + pd];
        float kp = row[C_ + h * 64 + pd];
        qv = qv * c + sign * qp * s;
        kv = kv * c + sign * kp * s;
    }

    size_t o = ((size_t)(b * H_ + h) * N_ + n) * DH_ + d;
    g_q[o] = qv; g_k[o] = kv; g_v[o] = vv;
}

// ---------------------------------------------------------------------------
// TF32 tensor-core flash attention. Grid: (N/64, B*H). 128 threads = 4 warps,
// warp w owns q-rows [16w, 16w+16). BK=64 keys per block.
// smem (dynamic, stride 68 words -> frag reads bank = 4*fr+fc, conflict-free):
//   sQ [64 q][68]  tf32 bits        sK [64 key][68] tf32 bits
//   sVt[64 d][68]  tf32 bits (V^T)  sP [64 q][68]   tf32 bits
// ---------------------------------------------------------------------------
#define ASTR 68
#define ATTN_SMEM_BYTES (4 * 64 * ASTR * 4)

__global__ void __launch_bounds__(128) attn_mma_kernel(float* __restrict__ out)
{
    extern __shared__ unsigned smu[];
    unsigned* sQ = smu;
    unsigned* sK = smu + 64 * ASTR;
    unsigned* sVt = smu + 2 * 64 * ASTR;
    unsigned* sP = smu + 3 * 64 * ASTR;

    const int t = threadIdx.x;
    const int lane = t & 31;
    const int w = t >> 5;
    const int fr = lane >> 2;     // 0..7
    const int fc = lane & 3;      // 0..3
    const int wm = w * 16;
    const int bh = blockIdx.y;
    const int q0 = blockIdx.x * 64;

    const float* Qg = g_q + ((size_t)bh * N_ + q0) * DH_;
    const float* Kg = g_k + (size_t)bh * N_ * DH_;
    const float* Vg = g_v + (size_t)bh * N_ * DH_;

    // Load Q tile (64x64) -> sQ, tf32-rounded
#pragma unroll
    for (int i = 0; i < 8; i++) {
        int idx4 = t + i * 128;
        int r = idx4 >> 4;
        int c4 = (idx4 & 15) * 4;
        float4 v4 = *(const float4*)(Qg + (size_t)r * 64 + c4);
        uint4 u = make_uint4(f2tf32(v4.x), f2tf32(v4.y), f2tf32(v4.z), f2tf32(v4.w));
        *(uint4*)&sQ[r * ASTR + c4] = u;
    }

    float m0 = -1e30f, m1 = -1e30f, l0 = 0.f, l1 = 0.f;
    float oacc[8][4];
#pragma unroll
    for (int nf = 0; nf < 8; nf++)
#pragma unroll
        for (int v = 0; v < 4; v++) oacc[nf][v] = 0.f;

    // V-transpose load mapping: d = 32*(w&1)+lane, key base = (w>>1)*4
    const int vd = 32 * (w & 1) + lane;
    const int vkb = (w >> 1) * 4;

    for (int kb = 0; kb < N_; kb += 64) {
        if (kb) __syncthreads();
        // K tile (64 keys x 64 d) -> sK direct (row = key)
#pragma unroll
        for (int i = 0; i < 8; i++) {
            int idx4 = t + i * 128;
            int r = idx4 >> 4;
            int c4 = (idx4 & 15) * 4;
            float4 k4 = *(const float4*)(Kg + (size_t)(kb + r) * 64 + c4);
            uint4 u = make_uint4(f2tf32(k4.x), f2tf32(k4.y), f2tf32(k4.z), f2tf32(k4.w));
            *(uint4*)&sK[r * ASTR + c4] = u;
        }
        // V tile transposed -> sVt[d][key]; 4 coalesced LDG.32 + 1 STS.128 per step
#pragma unroll
        for (int i = 0; i < 8; i++) {
            int key0 = vkb + i * 8;
            float v0 = Vg[(size_t)(kb + key0 + 0) * 64 + vd];
            float v1 = Vg[(size_t)(kb + key0 + 1) * 64 + vd];
            float v2 = Vg[(size_t)(kb + key0 + 2) * 64 + vd];
            float v3 = Vg[(size_t)(kb + key0 + 3) * 64 + vd];
            uint4 u = make_uint4(f2tf32(v0), f2tf32(v1), f2tf32(v2), f2tf32(v3));
            *(uint4*)&sVt[vd * ASTR + key0] = u;
        }
        __syncthreads();

        // S = Q K^T : warp-tile 16x64, 64 MMAs
        float sacc[8][4];
#pragma unroll
        for (int nf = 0; nf < 8; nf++)
#pragma unroll
            for (int v = 0; v < 4; v++) sacc[nf][v] = 0.f;
#pragma unroll
        for (int kc = 0; kc < 8; kc++) {
            unsigned a[4];
            const unsigned* ab = &sQ[(wm + fr) * ASTR + kc * 8 + fc];
            a[0] = ab[0]; a[1] = ab[8 * ASTR]; a[2] = ab[4]; a[3] = ab[8 * ASTR + 4];
#pragma unroll
            for (int nf = 0; nf < 8; nf++) {
                const unsigned* bb = &sK[(nf * 8 + fr) * ASTR + kc * 8 + fc];
                unsigned b[2] = {bb[0], bb[4]};
                mma_tf32(sacc[nf], a, b);
            }
        }

        // Online softmax. Thread owns rows (wm+fr) [regs 0,1] and (wm+fr+8) [2,3],
        // 16 cols spread over nf. Row is shared by the 4-lane quad (xor 1,2).
        const float scale = 0.125f;
        float rm0 = -1e30f, rm1 = -1e30f;
#pragma unroll
        for (int nf = 0; nf < 8; nf++) {
#pragma unroll
            for (int v = 0; v < 4; v++) sacc[nf][v] *= scale;
            rm0 = fmaxf(rm0, fmaxf(sacc[nf][0], sacc[nf][1]));
            rm1 = fmaxf(rm1, fmaxf(sacc[nf][2], sacc[nf][3]));
        }
#pragma unroll
        for (int off = 1; off < 4; off <<= 1) {
            rm0 = fmaxf(rm0, __shfl_xor_sync(0xffffffffu, rm0, off));
            rm1 = fmaxf(rm1, __shfl_xor_sync(0xffffffffu, rm1, off));
        }
        float mn0 = fmaxf(m0, rm0), mn1 = fmaxf(m1, rm1);
        float corr0 = __expf(m0 - mn0), corr1 = __expf(m1 - mn1);
        m0 = mn0; m1 = mn1;
        float rs0 = 0.f, rs1 = 0.f;
#pragma unroll
        for (int nf = 0; nf < 8; nf++) {
            float p0 = __expf(sacc[nf][0] - mn0);
            float p1 = __expf(sacc[nf][1] - mn0);
            float p2 = __expf(sacc[nf][2] - mn1);
            float p3 = __expf(sacc[nf][3] - mn1);
            sacc[nf][0] = p0; sacc[nf][1] = p1; sacc[nf][2] = p2; sacc[nf][3] = p3;
            rs0 += p0 + p1; rs1 += p2 + p3;
        }
#pragma unroll
        for (int off = 1; off < 4; off <<= 1) {
            rs0 += __shfl_xor_sync(0xffffffffu, rs0, off);
            rs1 += __shfl_xor_sync(0xffffffffu, rs1, off);
        }
        l0 = l0 * corr0 + rs0;
        l1 = l1 * corr1 + rs1;
#pragma unroll
        for (int nf = 0; nf < 8; nf++) {
            oacc[nf][0] *= corr0; oacc[nf][1] *= corr0;
            oacc[nf][2] *= corr1; oacc[nf][3] *= corr1;
        }

        // P -> sP (tf32 bits). Warp-private rows; within-warp cross-lane -> syncwarp.
#pragma unroll
        for (int nf = 0; nf < 8; nf++) {
            uint2 lo = make_uint2(f2tf32(sacc[nf][0]), f2tf32(sacc[nf][1]));
            uint2 hi = make_uint2(f2tf32(sacc[nf][2]), f2tf32(sacc[nf][3]));
            *(uint2*)&sP[(wm + fr) * ASTR + nf * 8 + 2 * fc] = lo;
            *(uint2*)&sP[(wm + fr + 8) * ASTR + nf * 8 + 2 * fc] = hi;
        }
        __syncwarp();

        // O += P * V : A from sP (k=key), B from sVt (n=d), 64 MMAs
#pragma unroll
        for (int kc = 0; kc < 8; kc++) {
            unsigned a[4];
            const unsigned* ab = &sP[(wm + fr) * ASTR + kc * 8 + fc];
            a[0] = ab[0]; a[1] = ab[8 * ASTR]; a[2] = ab[4]; a[3] = ab[8 * ASTR + 4];
#pragma unroll
            for (int nf = 0; nf < 8; nf++) {
                const unsigned* bb = &sVt[(nf * 8 + fr) * ASTR + kc * 8 + fc];
                unsigned b[2] = {bb[0], bb[4]};
                mma_tf32(oacc[nf], a, b);
            }
        }
    }

    // Epilogue: normalize and write to g_ao[b*N + q][h*64 + d]
    const float inv0 = 1.0f / l0;
    const float inv1 = 1.0f / l1;
    const int b = bh / H_;
    const int h = bh % H_;
    const int r0 = q0 + wm + fr;
#pragma unroll
    for (int nf = 0; nf < 8; nf++) {
        int col = h * 64 + nf * 8 + 2 * fc;
        float2 lo = make_float2(oacc[nf][0] * inv0, oacc[nf][1] * inv0);
        float2 hi = make_float2(oacc[nf][2] * inv1, oacc[nf][3] * inv1);
        *(float2*)(out + (size_t)(b * N_ + r0) * C_ + col) = lo;
        *(float2*)(out + (size_t)(b * N_ + r0 + 8) * C_ + col) = hi;
    }
}

// ---------------------------------------------------------------------------
extern "C" void kernel_launch(void* const* d_in, const int* in_sizes, int n_in,
                              void* d_out, int out_size)
{
    const float* x_t    = (const float*)d_in[0];
    const float* qkv_w  = (const float*)d_in[1];
    const float* qkv_b  = (const float*)d_in[2];
    const float* proj_w = (const float*)d_in[3];
    const float* proj_b = (const float*)d_in[4];
    const int*   pos2d  = (const int*)d_in[5];
    float* out = (float*)d_out;

    float *p_qkv, *p_ao;
    cudaGetSymbolAddress((void**)&p_qkv, g_qkv);
    cudaGetSymbolAddress((void**)&p_ao, g_ao);

    // 1) QKV GEMM: [8192,768] x [2304,768]^T -> [8192,2304]
    {
        dim3 grid((3 * C_) / 128, (B_ * N_) / 128);
        mma_gemm_bias<<<grid, 256>>>(x_t, qkv_w, qkv_b, p_qkv,
                                     B_ * N_, 3 * C_, C_);
    }
    // 2) RoPE2D + split/transpose
    {
        int total = B_ * N_ * H_ * DH_;
        rope_split_kernel<<<(total + 255) / 256, 256>>>(pos2d);
    }
    // 3) Attention (tf32 MMA)
    {
        cudaFuncSetAttribute(attn_mma_kernel,
                             cudaFuncAttributeMaxDynamicSharedMemorySize,
                             ATTN_SMEM_BYTES);
        dim3 grid(N_ / 64, B_ * H_);
        attn_mma_kernel<<<grid, 128, ATTN_SMEM_BYTES>>>(p_ao);
    }
    // 4) Output projection: [8192,768] x [768,768]^T -> [8192,768]
    {
        dim3 grid(C_ / 128, (B_ * N_) / 128);
        mma_gemm_bias<<<grid, 256>>>(p_ao, proj_w, proj_b, out,
                                     B_ * N_, C_, C_);
    }
}

// round 6
// speedup vs baseline: 4.4475x; 1.0549x over previous
#include <cuda_runtime.h>
#include <math.h>

#define B_ 8
#define N_ 1024
#define C_ 768
#define H_ 12
#define DH_ 64
#define NIMG_ 784

// Scratch (static device arrays: allocation-free per harness rules)
__device__ float g_qkv[B_ * N_ * 3 * C_];       // [8192][2304]
__device__ float g_q[B_ * H_ * N_ * DH_];       // [bh][n][d]
__device__ float g_k[B_ * H_ * N_ * DH_];
__device__ float g_v[B_ * H_ * N_ * DH_];
__device__ float g_ao[B_ * N_ * C_];            // attention out, [b*N+n][C]

__device__ __forceinline__ unsigned f2tf32(float f) {
    unsigned u;
    asm("cvt.rna.tf32.f32 %0, %1;" : "=r"(u) : "f"(f));
    return u;
}

__device__ __forceinline__ void mma_tf32(float* d, const unsigned* a, const unsigned* b) {
    asm volatile(
        "mma.sync.aligned.m16n8k8.row.col.f32.tf32.tf32.f32 "
        "{%0,%1,%2,%3}, {%4,%5,%6,%7}, {%8,%9}, {%0,%1,%2,%3};"
        : "+f"(d[0]), "+f"(d[1]), "+f"(d[2]), "+f"(d[3])
        : "r"(a[0]), "r"(a[1]), "r"(a[2]), "r"(a[3]), "r"(b[0]), "r"(b[1]));
}

// ---------------------------------------------------------------------------
// TF32 tensor-core GEMM, double-buffered smem (1 barrier / BK iteration).
// out[m][n] = dot(A[m][:], W[n][:]) + bias[n]
// A: [M][K] row-major, W: [Nout][K] row-major. Block 128x128, BK=16,
// 256 threads = 8 warps (2m x 4n), warp tile 64x32.
// Schedule: LDG(next) -> MMA(buf) -> cvt+STS(buf^1) -> sync.
// ---------------------------------------------------------------------------
#define BKg 16
#define SSTR 20  // smem row stride (uints): pad 4 -> conflict-free frag reads

__global__ void __launch_bounds__(256, 2) mma_gemm_bias(
    const float* __restrict__ A, const float* __restrict__ W,
    const float* __restrict__ bias, float* __restrict__ out,
    int M, int Nout, int K)
{
    __shared__ unsigned sA[2][128 * SSTR];
    __shared__ unsigned sB[2][128 * SSTR];

    const int t = threadIdx.x;
    const int lane = t & 31;
    const int warp = t >> 5;
    const int wm = (warp & 1) * 64;
    const int wn = (warp >> 1) * 32;
    const int m0 = blockIdx.y * 128;
    const int n0 = blockIdx.x * 128;

    const int r0g = (t + 0) >> 2, c0g = ((t + 0) & 3) * 4;
    const int r1g = (t + 256) >> 2, c1g = ((t + 256) & 3) * 4;

    float acc[4][4][4];
#pragma unroll
    for (int i = 0; i < 4; i++)
#pragma unroll
        for (int j = 0; j < 4; j++)
#pragma unroll
            for (int v = 0; v < 4; v++) acc[i][j][v] = 0.f;

    const int fr = lane >> 2;
    const int fc = lane & 3;

    float4 pa0, pa1, pb0, pb1;
    // tile 0 -> regs -> smem buf 0
    pa0 = *(const float4*)(A + (size_t)(m0 + r0g) * K + c0g);
    pa1 = *(const float4*)(A + (size_t)(m0 + r1g) * K + c1g);
    pb0 = *(const float4*)(W + (size_t)(n0 + r0g) * K + c0g);
    pb1 = *(const float4*)(W + (size_t)(n0 + r1g) * K + c1g);
    {
        uint4 ua0 = make_uint4(f2tf32(pa0.x), f2tf32(pa0.y), f2tf32(pa0.z), f2tf32(pa0.w));
        uint4 ua1 = make_uint4(f2tf32(pa1.x), f2tf32(pa1.y), f2tf32(pa1.z), f2tf32(pa1.w));
        uint4 ub0 = make_uint4(f2tf32(pb0.x), f2tf32(pb0.y), f2tf32(pb0.z), f2tf32(pb0.w));
        uint4 ub1 = make_uint4(f2tf32(pb1.x), f2tf32(pb1.y), f2tf32(pb1.z), f2tf32(pb1.w));
        *(uint4*)&sA[0][r0g * SSTR + c0g] = ua0;
        *(uint4*)&sA[0][r1g * SSTR + c1g] = ua1;
        *(uint4*)&sB[0][r0g * SSTR + c0g] = ub0;
        *(uint4*)&sB[0][r1g * SSTR + c1g] = ub1;
    }
    __syncthreads();

    const int nIter = K / BKg;
    for (int it = 0; it < nIter; it++) {
        const int buf = it & 1;
        const bool has_next = (it + 1) < nIter;

        // 1) issue next-tile global loads (latency hidden under MMAs)
        if (has_next) {
            int kn = (it + 1) * BKg;
            pa0 = *(const float4*)(A + (size_t)(m0 + r0g) * K + kn + c0g);
            pa1 = *(const float4*)(A + (size_t)(m0 + r1g) * K + kn + c1g);
            pb0 = *(const float4*)(W + (size_t)(n0 + r0g) * K + kn + c0g);
            pb1 = *(const float4*)(W + (size_t)(n0 + r1g) * K + kn + c1g);
        }

        // 2) MMAs on current buffer
        const unsigned* cA = sA[buf];
        const unsigned* cB = sB[buf];
#pragma unroll
        for (int ks = 0; ks < 2; ks++) {
            unsigned areg[4][4], breg[4][2];
#pragma unroll
            for (int mf = 0; mf < 4; mf++) {
                const unsigned* base = &cA[(wm + mf * 16 + fr) * SSTR + ks * 8 + fc];
                areg[mf][0] = base[0];
                areg[mf][1] = base[8 * SSTR];
                areg[mf][2] = base[4];
                areg[mf][3] = base[8 * SSTR + 4];
            }
#pragma unroll
            for (int nf = 0; nf < 4; nf++) {
                const unsigned* base = &cB[(wn + nf * 8 + fr) * SSTR + ks * 8 + fc];
                breg[nf][0] = base[0];
                breg[nf][1] = base[4];
            }
#pragma unroll
            for (int mf = 0; mf < 4; mf++)
#pragma unroll
                for (int nf = 0; nf < 4; nf++)
                    mma_tf32(acc[mf][nf], areg[mf], breg[nf]);
        }

        // 3) cvt + store next tile into the other buffer, 4) one barrier
        if (has_next) {
            unsigned* nA = sA[buf ^ 1];
            unsigned* nB = sB[buf ^ 1];
            uint4 ua0 = make_uint4(f2tf32(pa0.x), f2tf32(pa0.y), f2tf32(pa0.z), f2tf32(pa0.w));
            uint4 ua1 = make_uint4(f2tf32(pa1.x), f2tf32(pa1.y), f2tf32(pa1.z), f2tf32(pa1.w));
            uint4 ub0 = make_uint4(f2tf32(pb0.x), f2tf32(pb0.y), f2tf32(pb0.z), f2tf32(pb0.w));
            uint4 ub1 = make_uint4(f2tf32(pb1.x), f2tf32(pb1.y), f2tf32(pb1.z), f2tf32(pb1.w));
            *(uint4*)&nA[r0g * SSTR + c0g] = ua0;
            *(uint4*)&nA[r1g * SSTR + c1g] = ua1;
            *(uint4*)&nB[r0g * SSTR + c0g] = ub0;
            *(uint4*)&nB[r1g * SSTR + c1g] = ub1;
            __syncthreads();
        }
    }

    // epilogue
#pragma unroll
    for (int mf = 0; mf < 4; mf++) {
        int row = m0 + wm + mf * 16 + fr;
#pragma unroll
        for (int nf = 0; nf < 4; nf++) {
            int col = n0 + wn + nf * 8 + 2 * fc;
            float bx = bias[col], by = bias[col + 1];
            float2 lo = make_float2(acc[mf][nf][0] + bx, acc[mf][nf][1] + by);
            float2 hi = make_float2(acc[mf][nf][2] + bx, acc[mf][nf][3] + by);
            *(float2*)(out + (size_t)row * Nout + col) = lo;
            *(float2*)(out + (size_t)(row + 8) * Nout + col) = hi;
        }
    }
}

// ---------------------------------------------------------------------------
// RoPE2D + split qkv into q,k,v with [b*H+h][n][d] layout.
// ---------------------------------------------------------------------------
__global__ void rope_split_kernel(const int* __restrict__ pos2d)
{
    int idx = blockIdx.x * blockDim.x + threadIdx.x;
    const int total = B_ * N_ * H_ * DH_;
    if (idx >= total) return;

    int d = idx & 63;
    int h = (idx >> 6) % H_;
    int n = (idx / (H_ * DH_)) % N_;
    int b = idx / (N_ * H_ * DH_);

    const float* row = g_qkv + (size_t)(b * N_ + n) * (3 * C_);
    float qv = row[h * 64 + d];
    float kv = row[C_ + h * 64 + d];
    float vv = row[2 * C_ + h * 64 + d];

    if (n < NIMG_) {
        int half = d >> 5;
        int dl = d & 31;
        int f = dl & 15;
        int pos = pos2d[((size_t)b * NIMG_ + n) * 2 + half];
        float inv = exp2f(-0.41524101186f * (float)f);  // 100^(-f/16)
        float ang = (float)pos * inv;
        float s, c;
        sincosf(ang, &s, &c);
        int pd = (dl < 16) ? (d + 16) : (d - 16);
        float sign = (dl < 16) ? -1.0f : 1.0f;
        float qp = row[h * 64 + pd];
        float kp = row[C_ + h * 64 + pd];
        qv = qv * c + sign * qp * s;
        kv = kv * c + sign * kp * s;
    }

    size_t o = ((size_t)(b * H_ + h) * N_ + n) * DH_ + d;
    g_q[o] = qv; g_k[o] = kv; g_v[o] = vv;
}

// ---------------------------------------------------------------------------
// TF32 tensor-core flash attention (R5 measured-good). Grid: (N/64, B*H).
// 128 threads = 4 warps, warp w owns q-rows [16w,16w+16). BK=64.
// ---------------------------------------------------------------------------
#define ASTR 68
#define ATTN_SMEM_BYTES (4 * 64 * ASTR * 4)

__global__ void __launch_bounds__(128) attn_mma_kernel(float* __restrict__ out)
{
    extern __shared__ unsigned smu[];
    unsigned* sQ = smu;
    unsigned* sK = smu + 64 * ASTR;
    unsigned* sVt = smu + 2 * 64 * ASTR;
    unsigned* sP = smu + 3 * 64 * ASTR;

    const int t = threadIdx.x;
    const int lane = t & 31;
    const int w = t >> 5;
    const int fr = lane >> 2;
    const int fc = lane & 3;
    const int wm = w * 16;
    const int bh = blockIdx.y;
    const int q0 = blockIdx.x * 64;

    const float* Qg = g_q + ((size_t)bh * N_ + q0) * DH_;
    const float* Kg = g_k + (size_t)bh * N_ * DH_;
    const float* Vg = g_v + (size_t)bh * N_ * DH_;

#pragma unroll
    for (int i = 0; i < 8; i++) {
        int idx4 = t + i * 128;
        int r = idx4 >> 4;
        int c4 = (idx4 & 15) * 4;
        float4 v4 = *(const float4*)(Qg + (size_t)r * 64 + c4);
        uint4 u = make_uint4(f2tf32(v4.x), f2tf32(v4.y), f2tf32(v4.z), f2tf32(v4.w));
        *(uint4*)&sQ[r * ASTR + c4] = u;
    }

    float m0 = -1e30f, m1 = -1e30f, l0 = 0.f, l1 = 0.f;
    float oacc[8][4];
#pragma unroll
    for (int nf = 0; nf < 8; nf++)
#pragma unroll
        for (int v = 0; v < 4; v++) oacc[nf][v] = 0.f;

    const int vd = 32 * (w & 1) + lane;
    const int vkb = (w >> 1) * 4;

    for (int kb = 0; kb < N_; kb += 64) {
        if (kb) __syncthreads();
#pragma unroll
        for (int i = 0; i < 8; i++) {
            int idx4 = t + i * 128;
            int r = idx4 >> 4;
            int c4 = (idx4 & 15) * 4;
            float4 k4 = *(const float4*)(Kg + (size_t)(kb + r) * 64 + c4);
            uint4 u = make_uint4(f2tf32(k4.x), f2tf32(k4.y), f2tf32(k4.z), f2tf32(k4.w));
            *(uint4*)&sK[r * ASTR + c4] = u;
        }
#pragma unroll
        for (int i = 0; i < 8; i++) {
            int key0 = vkb + i * 8;
            float v0 = Vg[(size_t)(kb + key0 + 0) * 64 + vd];
            float v1 = Vg[(size_t)(kb + key0 + 1) * 64 + vd];
            float v2 = Vg[(size_t)(kb + key0 + 2) * 64 + vd];
            float v3 = Vg[(size_t)(kb + key0 + 3) * 64 + vd];
            uint4 u = make_uint4(f2tf32(v0), f2tf32(v1), f2tf32(v2), f2tf32(v3));
            *(uint4*)&sVt[vd * ASTR + key0] = u;
        }
        __syncthreads();

        float sacc[8][4];
#pragma unroll
        for (int nf = 0; nf < 8; nf++)
#pragma unroll
            for (int v = 0; v < 4; v++) sacc[nf][v] = 0.f;
#pragma unroll
        for (int kc = 0; kc < 8; kc++) {
            unsigned a[4];
            const unsigned* ab = &sQ[(wm + fr) * ASTR + kc * 8 + fc];
            a[0] = ab[0]; a[1] = ab[8 * ASTR]; a[2] = ab[4]; a[3] = ab[8 * ASTR + 4];
#pragma unroll
            for (int nf = 0; nf < 8; nf++) {
                const unsigned* bb = &sK[(nf * 8 + fr) * ASTR + kc * 8 + fc];
                unsigned b[2] = {bb[0], bb[4]};
                mma_tf32(sacc[nf], a, b);
            }
        }

        const float scale = 0.125f;
        float rm0 = -1e30f, rm1 = -1e30f;
#pragma unroll
        for (int nf = 0; nf < 8; nf++) {
#pragma unroll
            for (int v = 0; v < 4; v++) sacc[nf][v] *= scale;
            rm0 = fmaxf(rm0, fmaxf(sacc[nf][0], sacc[nf][1]));
            rm1 = fmaxf(rm1, fmaxf(sacc[nf][2], sacc[nf][3]));
        }
#pragma unroll
        for (int off = 1; off < 4; off <<= 1) {
            rm0 = fmaxf(rm0, __shfl_xor_sync(0xffffffffu, rm0, off));
            rm1 = fmaxf(rm1, __shfl_xor_sync(0xffffffffu, rm1, off));
        }
        float mn0 = fmaxf(m0, rm0), mn1 = fmaxf(m1, rm1);
        float corr0 = __expf(m0 - mn0), corr1 = __expf(m1 - mn1);
        m0 = mn0; m1 = mn1;
        float rs0 = 0.f, rs1 = 0.f;
#pragma unroll
        for (int nf = 0; nf < 8; nf++) {
            float p0 = __expf(sacc[nf][0] - mn0);
            float p1 = __expf(sacc[nf][1] - mn0);
            float p2 = __expf(sacc[nf][2] - mn1);
            float p3 = __expf(sacc[nf][3] - mn1);
            sacc[nf][0] = p0; sacc[nf][1] = p1; sacc[nf][2] = p2; sacc[nf][3] = p3;
            rs0 += p0 + p1; rs1 += p2 + p3;
        }
#pragma unroll
        for (int off = 1; off < 4; off <<= 1) {
            rs0 += __shfl_xor_sync(0xffffffffu, rs0, off);
            rs1 += __shfl_xor_sync(0xffffffffu, rs1, off);
        }
        l0 = l0 * corr0 + rs0;
        l1 = l1 * corr1 + rs1;
#pragma unroll
        for (int nf = 0; nf < 8; nf++) {
            oacc[nf][0] *= corr0; oacc[nf][1] *= corr0;
            oacc[nf][2] *= corr1; oacc[nf][3] *= corr1;
        }

#pragma unroll
        for (int nf = 0; nf < 8; nf++) {
            uint2 lo = make_uint2(f2tf32(sacc[nf][0]), f2tf32(sacc[nf][1]));
            uint2 hi = make_uint2(f2tf32(sacc[nf][2]), f2tf32(sacc[nf][3]));
            *(uint2*)&sP[(wm + fr) * ASTR + nf * 8 + 2 * fc] = lo;
            *(uint2*)&sP[(wm + fr + 8) * ASTR + nf * 8 + 2 * fc] = hi;
        }
        __syncwarp();

#pragma unroll
        for (int kc = 0; kc < 8; kc++) {
            unsigned a[4];
            const unsigned* ab = &sP[(wm + fr) * ASTR + kc * 8 + fc];
            a[0] = ab[0]; a[1] = ab[8 * ASTR]; a[2] = ab[4]; a[3] = ab[8 * ASTR + 4];
#pragma unroll
            for (int nf = 0; nf < 8; nf++) {
                const unsigned* bb = &sVt[(nf * 8 + fr) * ASTR + kc * 8 + fc];
                unsigned b[2] = {bb[0], bb[4]};
                mma_tf32(oacc[nf], a, b);
            }
        }
    }

    const float inv0 = 1.0f / l0;
    const float inv1 = 1.0f / l1;
    const int b = bh / H_;
    const int h = bh % H_;
    const int r0 = q0 + wm + fr;
#pragma unroll
    for (int nf = 0; nf < 8; nf++) {
        int col = h * 64 + nf * 8 + 2 * fc;
        float2 lo = make_float2(oacc[nf][0] * inv0, oacc[nf][1] * inv0);
        float2 hi = make_float2(oacc[nf][2] * inv1, oacc[nf][3] * inv1);
        *(float2*)(out + (size_t)(b * N_ + r0) * C_ + col) = lo;
        *(float2*)(out + (size_t)(b * N_ + r0 + 8) * C_ + col) = hi;
    }
}

// ---------------------------------------------------------------------------
extern "C" void kernel_launch(void* const* d_in, const int* in_sizes, int n_in,
                              void* d_out, int out_size)
{
    const float* x_t    = (const float*)d_in[0];
    const float* qkv_w  = (const float*)d_in[1];
    const float* qkv_b  = (const float*)d_in[2];
    const float* proj_w = (const float*)d_in[3];
    const float* proj_b = (const float*)d_in[4];
    const int*   pos2d  = (const int*)d_in[5];
    float* out = (float*)d_out;

    float *p_qkv, *p_ao;
    cudaGetSymbolAddress((void**)&p_qkv, g_qkv);
    cudaGetSymbolAddress((void**)&p_ao, g_ao);

    // 1) QKV GEMM: [8192,768] x [2304,768]^T -> [8192,2304]
    {
        dim3 grid((3 * C_) / 128, (B_ * N_) / 128);
        mma_gemm_bias<<<grid, 256>>>(x_t, qkv_w, qkv_b, p_qkv,
                                     B_ * N_, 3 * C_, C_);
    }
    // 2) RoPE2D + split/transpose
    {
        int total = B_ * N_ * H_ * DH_;
        rope_split_kernel<<<(total + 255) / 256, 256>>>(pos2d);
    }
    // 3) Attention (tf32 MMA)
    {
        cudaFuncSetAttribute(attn_mma_kernel,
                             cudaFuncAttributeMaxDynamicSharedMemorySize,
                             ATTN_SMEM_BYTES);
        dim3 grid(N_ / 64, B_ * H_);
        attn_mma_kernel<<<grid, 128, ATTN_SMEM_BYTES>>>(p_ao);
    }
    // 4) Output projection: [8192,768] x [768,768]^T -> [8192,768]
    {
        dim3 grid(C_ / 128, (B_ * N_) / 128);
        mma_gemm_bias<<<grid, 256>>>(p_ao, proj_w, proj_b, out,
                                     B_ * N_, C_, C_);
    }
}

// round 7
// speedup vs baseline: 5.1238x; 1.1521x over previous
#include <cuda_runtime.h>
#include <math.h>

#define B_ 8
#define N_ 1024
#define C_ 768
#define H_ 12
#define DH_ 64
#define NIMG_ 784

// Scratch (static device arrays: allocation-free per harness rules)
__device__ float g_qkv[B_ * N_ * 3 * C_];       // [8192][2304]
__device__ float g_q[B_ * H_ * N_ * DH_];       // [bh][n][d]
__device__ float g_k[B_ * H_ * N_ * DH_];
__device__ float g_v[B_ * H_ * N_ * DH_];
__device__ float g_ao[B_ * N_ * C_];            // attention out, [b*N+n][C]

__device__ __forceinline__ unsigned f2tf32(float f) {
    unsigned u;
    asm("cvt.rna.tf32.f32 %0, %1;" : "=r"(u) : "f"(f));
    return u;
}

__device__ __forceinline__ void mma_tf32(float* d, const unsigned* a, const unsigned* b) {
    asm volatile(
        "mma.sync.aligned.m16n8k8.row.col.f32.tf32.tf32.f32 "
        "{%0,%1,%2,%3}, {%4,%5,%6,%7}, {%8,%9}, {%0,%1,%2,%3};"
        : "+f"(d[0]), "+f"(d[1]), "+f"(d[2]), "+f"(d[3])
        : "r"(a[0]), "r"(a[1]), "r"(a[2]), "r"(a[3]), "r"(b[0]), "r"(b[1]));
}

__device__ __forceinline__ unsigned sptr(const void* p) {
    return (unsigned)__cvta_generic_to_shared(p);
}

// One ldmatrix.x4 = four 8x4-b32 tiles = a full tf32 A-fragment (or two B-frags)
__device__ __forceinline__ void ldsm_x4(unsigned& r0, unsigned& r1,
                                        unsigned& r2, unsigned& r3, unsigned addr) {
    asm volatile("ldmatrix.sync.aligned.m8n8.x4.shared.b16 {%0,%1,%2,%3}, [%4];"
        : "=r"(r0), "=r"(r1), "=r"(r2), "=r"(r3) : "r"(addr));
}

// ---------------------------------------------------------------------------
// TF32 tensor-core GEMM, double-buffered smem + LDSM fragment loads.
// out[m][n] = dot(A[m][:], W[n][:]) + bias[n]
// Block 128x128, BK=16, 256 threads = 8 warps (2m x 4n), warp tile 64x32.
// ---------------------------------------------------------------------------
#define BKg 16
#define SSTR 20  // smem row stride (uints): rows 16B-aligned, LDSM conflict-free

__global__ void __launch_bounds__(256, 2) mma_gemm_bias(
    const float* __restrict__ A, const float* __restrict__ W,
    const float* __restrict__ bias, float* __restrict__ out,
    int M, int Nout, int K)
{
    __shared__ __align__(16) unsigned sA[2][128 * SSTR];
    __shared__ __align__(16) unsigned sB[2][128 * SSTR];

    const int t = threadIdx.x;
    const int lane = t & 31;
    const int warp = t >> 5;
    const int wm = (warp & 1) * 64;
    const int wn = (warp >> 1) * 32;
    const int m0 = blockIdx.y * 128;
    const int n0 = blockIdx.x * 128;

    const int r0g = (t + 0) >> 2, c0g = ((t + 0) & 3) * 4;
    const int r1g = (t + 256) >> 2, c1g = ((t + 256) & 3) * 4;

    // LDSM per-lane row-address offsets (in words)
    const int lg = lane >> 3, lr = lane & 7;
    // A-frag: m0=(r,c0-3) m1=(r+8,c0-3) m2=(r,c4-7) m3=(r+8,c4-7)
    const int a_off = ((lg & 1) * 8 + lr) * SSTR + (lg >> 1) * 4;
    // B-pair: m0=(n+r,k0-3) m1=(n+r,k4-7) m2=(n+8+r,k0-3) m3=(n+8+r,k4-7)
    const int b_off = ((lg >> 1) * 8 + lr) * SSTR + (lg & 1) * 4;

    float acc[4][4][4];
#pragma unroll
    for (int i = 0; i < 4; i++)
#pragma unroll
        for (int j = 0; j < 4; j++)
#pragma unroll
            for (int v = 0; v < 4; v++) acc[i][j][v] = 0.f;

    const int fr = lane >> 2;
    const int fc = lane & 3;

    float4 pa0, pa1, pb0, pb1;
    pa0 = *(const float4*)(A + (size_t)(m0 + r0g) * K + c0g);
    pa1 = *(const float4*)(A + (size_t)(m0 + r1g) * K + c1g);
    pb0 = *(const float4*)(W + (size_t)(n0 + r0g) * K + c0g);
    pb1 = *(const float4*)(W + (size_t)(n0 + r1g) * K + c1g);
    {
        uint4 ua0 = make_uint4(f2tf32(pa0.x), f2tf32(pa0.y), f2tf32(pa0.z), f2tf32(pa0.w));
        uint4 ua1 = make_uint4(f2tf32(pa1.x), f2tf32(pa1.y), f2tf32(pa1.z), f2tf32(pa1.w));
        uint4 ub0 = make_uint4(f2tf32(pb0.x), f2tf32(pb0.y), f2tf32(pb0.z), f2tf32(pb0.w));
        uint4 ub1 = make_uint4(f2tf32(pb1.x), f2tf32(pb1.y), f2tf32(pb1.z), f2tf32(pb1.w));
        *(uint4*)&sA[0][r0g * SSTR + c0g] = ua0;
        *(uint4*)&sA[0][r1g * SSTR + c1g] = ua1;
        *(uint4*)&sB[0][r0g * SSTR + c0g] = ub0;
        *(uint4*)&sB[0][r1g * SSTR + c1g] = ub1;
    }
    __syncthreads();

    const int nIter = K / BKg;
    for (int it = 0; it < nIter; it++) {
        const int buf = it & 1;
        const bool has_next = (it + 1) < nIter;

        if (has_next) {
            int kn = (it + 1) * BKg;
            pa0 = *(const float4*)(A + (size_t)(m0 + r0g) * K + kn + c0g);
            pa1 = *(const float4*)(A + (size_t)(m0 + r1g) * K + kn + c1g);
            pb0 = *(const float4*)(W + (size_t)(n0 + r0g) * K + kn + c0g);
            pb1 = *(const float4*)(W + (size_t)(n0 + r1g) * K + kn + c1g);
        }

        const unsigned* cA = sA[buf];
        const unsigned* cB = sB[buf];
#pragma unroll
        for (int ks = 0; ks < 2; ks++) {
            unsigned areg[4][4], breg[4][2];
#pragma unroll
            for (int mf = 0; mf < 4; mf++)
                ldsm_x4(areg[mf][0], areg[mf][1], areg[mf][2], areg[mf][3],
                        sptr(cA + (wm + mf * 16) * SSTR + ks * 8 + a_off));
#pragma unroll
            for (int np = 0; np < 2; np++)
                ldsm_x4(breg[np * 2][0], breg[np * 2][1],
                        breg[np * 2 + 1][0], breg[np * 2 + 1][1],
                        sptr(cB + (wn + np * 16) * SSTR + ks * 8 + b_off));
#pragma unroll
            for (int mf = 0; mf < 4; mf++)
#pragma unroll
                for (int nf = 0; nf < 4; nf++)
                    mma_tf32(acc[mf][nf], areg[mf], breg[nf]);
        }

        if (has_next) {
            unsigned* nA = sA[buf ^ 1];
            unsigned* nB = sB[buf ^ 1];
            uint4 ua0 = make_uint4(f2tf32(pa0.x), f2tf32(pa0.y), f2tf32(pa0.z), f2tf32(pa0.w));
            uint4 ua1 = make_uint4(f2tf32(pa1.x), f2tf32(pa1.y), f2tf32(pa1.z), f2tf32(pa1.w));
            uint4 ub0 = make_uint4(f2tf32(pb0.x), f2tf32(pb0.y), f2tf32(pb0.z), f2tf32(pb0.w));
            uint4 ub1 = make_uint4(f2tf32(pb1.x), f2tf32(pb1.y), f2tf32(pb1.z), f2tf32(pb1.w));
            *(uint4*)&nA[r0g * SSTR + c0g] = ua0;
            *(uint4*)&nA[r1g * SSTR + c1g] = ua1;
            *(uint4*)&nB[r0g * SSTR + c0g] = ub0;
            *(uint4*)&nB[r1g * SSTR + c1g] = ub1;
            __syncthreads();
        }
    }

#pragma unroll
    for (int mf = 0; mf < 4; mf++) {
        int row = m0 + wm + mf * 16 + fr;
#pragma unroll
        for (int nf = 0; nf < 4; nf++) {
            int col = n0 + wn + nf * 8 + 2 * fc;
            float bx = bias[col], by = bias[col + 1];
            float2 lo = make_float2(acc[mf][nf][0] + bx, acc[mf][nf][1] + by);
            float2 hi = make_float2(acc[mf][nf][2] + bx, acc[mf][nf][3] + by);
            *(float2*)(out + (size_t)row * Nout + col) = lo;
            *(float2*)(out + (size_t)(row + 8) * Nout + col) = hi;
        }
    }
}

// ---------------------------------------------------------------------------
// RoPE2D + split qkv into q,k,v with [b*H+h][n][d] layout.
// ---------------------------------------------------------------------------
__global__ void rope_split_kernel(const int* __restrict__ pos2d)
{
    int idx = blockIdx.x * blockDim.x + threadIdx.x;
    const int total = B_ * N_ * H_ * DH_;
    if (idx >= total) return;

    int d = idx & 63;
    int h = (idx >> 6) % H_;
    int n = (idx / (H_ * DH_)) % N_;
    int b = idx / (N_ * H_ * DH_);

    const float* row = g_qkv + (size_t)(b * N_ + n) * (3 * C_);
    float qv = row[h * 64 + d];
    float kv = row[C_ + h * 64 + d];
    float vv = row[2 * C_ + h * 64 + d];

    if (n < NIMG_) {
        int half = d >> 5;
        int dl = d & 31;
        int f = dl & 15;
        int pos = pos2d[((size_t)b * NIMG_ + n) * 2 + half];
        float inv = exp2f(-0.41524101186f * (float)f);  // 100^(-f/16)
        float ang = (float)pos * inv;
        float s, c;
        sincosf(ang, &s, &c);
        int pd = (dl < 16) ? (d + 16) : (d - 16);
        float sign = (dl < 16) ? -1.0f : 1.0f;
        float qp = row[h * 64 + pd];
        float kp = row[C_ + h * 64 + pd];
        qv = qv * c + sign * qp * s;
        kv = kv * c + sign * kp * s;
    }

    size_t o = ((size_t)(b * H_ + h) * N_ + n) * DH_ + d;
    g_q[o] = qv; g_k[o] = kv; g_v[o] = vv;
}

// ---------------------------------------------------------------------------
// TF32 tensor-core flash attention + LDSM fragment loads.
// Grid: (N/64, B*H). 128 threads = 4 warps, warp w owns q-rows [16w,16w+16).
// ---------------------------------------------------------------------------
#define ASTR 68
#define ATTN_SMEM_BYTES (4 * 64 * ASTR * 4)

__global__ void __launch_bounds__(128) attn_mma_kernel(float* __restrict__ out)
{
    extern __shared__ __align__(16) unsigned smu[];
    unsigned* sQ = smu;
    unsigned* sK = smu + 64 * ASTR;
    unsigned* sVt = smu + 2 * 64 * ASTR;
    unsigned* sP = smu + 3 * 64 * ASTR;

    const int t = threadIdx.x;
    const int lane = t & 31;
    const int w = t >> 5;
    const int fr = lane >> 2;
    const int fc = lane & 3;
    const int wm = w * 16;
    const int bh = blockIdx.y;
    const int q0 = blockIdx.x * 64;

    // LDSM per-lane offsets (words, stride ASTR)
    const int lg = lane >> 3, lr = lane & 7;
    const int a_off = ((lg & 1) * 8 + lr) * ASTR + (lg >> 1) * 4;
    const int b_off = ((lg >> 1) * 8 + lr) * ASTR + (lg & 1) * 4;

    const float* Qg = g_q + ((size_t)bh * N_ + q0) * DH_;
    const float* Kg = g_k + (size_t)bh * N_ * DH_;
    const float* Vg = g_v + (size_t)bh * N_ * DH_;

#pragma unroll
    for (int i = 0; i < 8; i++) {
        int idx4 = t + i * 128;
        int r = idx4 >> 4;
        int c4 = (idx4 & 15) * 4;
        float4 v4 = *(const float4*)(Qg + (size_t)r * 64 + c4);
        uint4 u = make_uint4(f2tf32(v4.x), f2tf32(v4.y), f2tf32(v4.z), f2tf32(v4.w));
        *(uint4*)&sQ[r * ASTR + c4] = u;
    }

    float m0 = -1e30f, m1 = -1e30f, l0 = 0.f, l1 = 0.f;
    float oacc[8][4];
#pragma unroll
    for (int nf = 0; nf < 8; nf++)
#pragma unroll
        for (int v = 0; v < 4; v++) oacc[nf][v] = 0.f;

    const int vd = 32 * (w & 1) + lane;
    const int vkb = (w >> 1) * 4;

    for (int kb = 0; kb < N_; kb += 64) {
        if (kb) __syncthreads();
#pragma unroll
        for (int i = 0; i < 8; i++) {
            int idx4 = t + i * 128;
            int r = idx4 >> 4;
            int c4 = (idx4 & 15) * 4;
            float4 k4 = *(const float4*)(Kg + (size_t)(kb + r) * 64 + c4);
            uint4 u = make_uint4(f2tf32(k4.x), f2tf32(k4.y), f2tf32(k4.z), f2tf32(k4.w));
            *(uint4*)&sK[r * ASTR + c4] = u;
        }
#pragma unroll
        for (int i = 0; i < 8; i++) {
            int key0 = vkb + i * 8;
            float v0 = Vg[(size_t)(kb + key0 + 0) * 64 + vd];
            float v1 = Vg[(size_t)(kb + key0 + 1) * 64 + vd];
            float v2 = Vg[(size_t)(kb + key0 + 2) * 64 + vd];
            float v3 = Vg[(size_t)(kb + key0 + 3) * 64 + vd];
            uint4 u = make_uint4(f2tf32(v0), f2tf32(v1), f2tf32(v2), f2tf32(v3));
            *(uint4*)&sVt[vd * ASTR + key0] = u;
        }
        __syncthreads();

        // S = Q K^T : 8 kc-steps, LDSM frags
        float sacc[8][4];
#pragma unroll
        for (int nf = 0; nf < 8; nf++)
#pragma unroll
            for (int v = 0; v < 4; v++) sacc[nf][v] = 0.f;
#pragma unroll
        for (int kc = 0; kc < 8; kc++) {
            unsigned a[4], breg[8][2];
            ldsm_x4(a[0], a[1], a[2], a[3], sptr(sQ + wm * ASTR + kc * 8 + a_off));
#pragma unroll
            for (int np = 0; np < 4; np++)
                ldsm_x4(breg[np * 2][0], breg[np * 2][1],
                        breg[np * 2 + 1][0], breg[np * 2 + 1][1],
                        sptr(sK + np * 16 * ASTR + kc * 8 + b_off));
#pragma unroll
            for (int nf = 0; nf < 8; nf++)
                mma_tf32(sacc[nf], a, breg[nf]);
        }

        const float scale = 0.125f;
        float rm0 = -1e30f, rm1 = -1e30f;
#pragma unroll
        for (int nf = 0; nf < 8; nf++) {
#pragma unroll
            for (int v = 0; v < 4; v++) sacc[nf][v] *= scale;
            rm0 = fmaxf(rm0, fmaxf(sacc[nf][0], sacc[nf][1]));
            rm1 = fmaxf(rm1, fmaxf(sacc[nf][2], sacc[nf][3]));
        }
#pragma unroll
        for (int off = 1; off < 4; off <<= 1) {
            rm0 = fmaxf(rm0, __shfl_xor_sync(0xffffffffu, rm0, off));
            rm1 = fmaxf(rm1, __shfl_xor_sync(0xffffffffu, rm1, off));
        }
        float mn0 = fmaxf(m0, rm0), mn1 = fmaxf(m1, rm1);
        float corr0 = __expf(m0 - mn0), corr1 = __expf(m1 - mn1);
        m0 = mn0; m1 = mn1;
        float rs0 = 0.f, rs1 = 0.f;
#pragma unroll
        for (int nf = 0; nf < 8; nf++) {
            float p0 = __expf(sacc[nf][0] - mn0);
            float p1 = __expf(sacc[nf][1] - mn0);
            float p2 = __expf(sacc[nf][2] - mn1);
            float p3 = __expf(sacc[nf][3] - mn1);
            sacc[nf][0] = p0; sacc[nf][1] = p1; sacc[nf][2] = p2; sacc[nf][3] = p3;
            rs0 += p0 + p1; rs1 += p2 + p3;
        }
#pragma unroll
        for (int off = 1; off < 4; off <<= 1) {
            rs0 += __shfl_xor_sync(0xffffffffu, rs0, off);
            rs1 += __shfl_xor_sync(0xffffffffu, rs1, off);
        }
        l0 = l0 * corr0 + rs0;
        l1 = l1 * corr1 + rs1;
#pragma unroll
        for (int nf = 0; nf < 8; nf++) {
            oacc[nf][0] *= corr0; oacc[nf][1] *= corr0;
            oacc[nf][2] *= corr1; oacc[nf][3] *= corr1;
        }

#pragma unroll
        for (int nf = 0; nf < 8; nf++) {
            uint2 lo = make_uint2(f2tf32(sacc[nf][0]), f2tf32(sacc[nf][1]));
            uint2 hi = make_uint2(f2tf32(sacc[nf][2]), f2tf32(sacc[nf][3]));
            *(uint2*)&sP[(wm + fr) * ASTR + nf * 8 + 2 * fc] = lo;
            *(uint2*)&sP[(wm + fr + 8) * ASTR + nf * 8 + 2 * fc] = hi;
        }
        __syncwarp();

        // O += P * V : LDSM frags (A from sP, B from sVt)
#pragma unroll
        for (int kc = 0; kc < 8; kc++) {
            unsigned a[4], breg[8][2];
            ldsm_x4(a[0], a[1], a[2], a[3], sptr(sP + wm * ASTR + kc * 8 + a_off));
#pragma unroll
            for (int np = 0; np < 4; np++)
                ldsm_x4(breg[np * 2][0], breg[np * 2][1],
                        breg[np * 2 + 1][0], breg[np * 2 + 1][1],
                        sptr(sVt + np * 16 * ASTR + kc * 8 + b_off));
#pragma unroll
            for (int nf = 0; nf < 8; nf++)
                mma_tf32(oacc[nf], a, breg[nf]);
        }
    }

    const float inv0 = 1.0f / l0;
    const float inv1 = 1.0f / l1;
    const int b = bh / H_;
    const int h = bh % H_;
    const int r0 = q0 + wm + fr;
#pragma unroll
    for (int nf = 0; nf < 8; nf++) {
        int col = h * 64 + nf * 8 + 2 * fc;
        float2 lo = make_float2(oacc[nf][0] * inv0, oacc[nf][1] * inv0);
        float2 hi = make_float2(oacc[nf][2] * inv1, oacc[nf][3] * inv1);
        *(float2*)(out + (size_t)(b * N_ + r0) * C_ + col) = lo;
        *(float2*)(out + (size_t)(b * N_ + r0 + 8) * C_ + col) = hi;
    }
}

// ---------------------------------------------------------------------------
extern "C" void kernel_launch(void* const* d_in, const int* in_sizes, int n_in,
                              void* d_out, int out_size)
{
    const float* x_t    = (const float*)d_in[0];
    const float* qkv_w  = (const float*)d_in[1];
    const float* qkv_b  = (const float*)d_in[2];
    const float* proj_w = (const float*)d_in[3];
    const float* proj_b = (const float*)d_in[4];
    const int*   pos2d  = (const int*)d_in[5];
    float* out = (float*)d_out;

    float *p_qkv, *p_ao;
    cudaGetSymbolAddress((void**)&p_qkv, g_qkv);
    cudaGetSymbolAddress((void**)&p_ao, g_ao);

    // 1) QKV GEMM: [8192,768] x [2304,768]^T -> [8192,2304]
    {
        dim3 grid((3 * C_) / 128, (B_ * N_) / 128);
        mma_gemm_bias<<<grid, 256>>>(x_t, qkv_w, qkv_b, p_qkv,
                                     B_ * N_, 3 * C_, C_);
    }
    // 2) RoPE2D + split/transpose
    {
        int total = B_ * N_ * H_ * DH_;
        rope_split_kernel<<<(total + 255) / 256, 256>>>(pos2d);
    }
    // 3) Attention (tf32 MMA + LDSM)
    {
        cudaFuncSetAttribute(attn_mma_kernel,
                             cudaFuncAttributeMaxDynamicSharedMemorySize,
                             ATTN_SMEM_BYTES);
        dim3 grid(N_ / 64, B_ * H_);
        attn_mma_kernel<<<grid, 128, ATTN_SMEM_BYTES>>>(p_ao);
    }
    // 4) Output projection: [8192,768] x [768,768]^T -> [8192,768]
    {
        dim3 grid(C_ / 128, (B_ * N_) / 128);
        mma_gemm_bias<<<grid, 256>>>(p_ao, proj_w, proj_b, out,
                                     B_ * N_, C_, C_);
    }
}